// round 16
// baseline (speedup 1.0000x reference)
#include <cuda_runtime.h>
#include <cuda_fp16.h>
#include <stdint.h>
#include <math.h>

// Problem constants
#define BB 16
#define CC 512
#define NN 2304      // 48*48
#define II 64
#define NTM 18       // m-tiles per row (2304/128)

// ---------------- scratch (static device globals; no allocation) ----------------
__device__ __half g_qth[(size_t)BB * NN * II];        // 4.7 MB qT hi [n][i]
__device__ __half g_qtl[(size_t)BB * NN * II];        // 4.7 MB qT lo
__device__ __half g_kth[(size_t)BB * NN * II];        // 4.7 MB kT hi [m][i]
__device__ __half g_ktl[(size_t)BB * NN * II];        // 4.7 MB kT lo
__device__ __half g_ph[(size_t)BB * NN * NN];         // 162 MB fp16 P (unnorm, then normalized)
__device__ float  g_mrow[(size_t)BB * NTM * NN];      // 2.7 MB per-tile row max
__device__ float  g_srow[(size_t)BB * NTM * NN];      // 2.7 MB per-tile row expsum
__device__ __half g_vh[(size_t)BB * CC * NN];         //  36 MB fp16 V
__device__ __half g_xth[(size_t)BB * NN * CC];        //  74 MB fp16 xT [n][c]
__device__ float  g_wqk[128 * CC];                    // [Wq; Wk] concat fp32
__device__ __half g_wvh[CC * CC];                     // Wv fp16

// =====================================================================
// helpers
// =====================================================================
__device__ __forceinline__ uint32_t smem_u32(const void* p) {
    uint32_t a;
    asm("{ .reg .u64 t; cvta.to.shared.u64 t, %1; cvt.u32.u64 %0, t; }"
        : "=r"(a) : "l"(p));
    return a;
}

__device__ __forceinline__ void cp_async16(uint32_t saddr, const void* gptr) {
    asm volatile("cp.async.cg.shared.global [%0], [%1], 16;"
                 :: "r"(saddr), "l"(gptr) : "memory");
}
__device__ __forceinline__ void cp_commit() {
    asm volatile("cp.async.commit_group;" ::: "memory");
}
template<int N>
__device__ __forceinline__ void cp_wait() {
    asm volatile("cp.async.wait_group %0;" :: "n"(N) : "memory");
}

// fp16: D += A(16x16) * B(16x8), fp32 accumulate
__device__ __forceinline__ void mma168816(float* d, const uint32_t* a, const uint32_t* b) {
    asm volatile(
        "mma.sync.aligned.m16n8k16.row.col.f32.f16.f16.f32 "
        "{%0,%1,%2,%3}, {%4,%5,%6,%7}, {%8,%9}, {%0,%1,%2,%3};"
        : "+f"(d[0]), "+f"(d[1]), "+f"(d[2]), "+f"(d[3])
        : "r"(a[0]), "r"(a[1]), "r"(a[2]), "r"(a[3]), "r"(b[0]), "r"(b[1]));
}

// ldmatrix: 4x / 2x 8x8 b16 matrices from shared
__device__ __forceinline__ void ldsm_x4(uint32_t* r, uint32_t addr) {
    asm volatile("ldmatrix.sync.aligned.m8n8.x4.shared.b16 {%0,%1,%2,%3}, [%4];"
                 : "=r"(r[0]), "=r"(r[1]), "=r"(r[2]), "=r"(r[3]) : "r"(addr));
}
__device__ __forceinline__ void ldsm_x2(uint32_t* r, uint32_t addr) {
    asm volatile("ldmatrix.sync.aligned.m8n8.x2.shared.b16 {%0,%1}, [%2];"
                 : "=r"(r[0]), "=r"(r[1]) : "r"(addr));
}

// =====================================================================
// prep: concat [Wq;Wk] fp32, convert Wv -> fp16
// =====================================================================
__global__ __launch_bounds__(256)
void prep_w_kernel(const float* __restrict__ Wq, const float* __restrict__ Wk,
                   const float* __restrict__ Wv)
{
    const int i = blockIdx.x * blockDim.x + threadIdx.x;
    if (i < 128 * CC)
        g_wqk[i] = (i < II * CC) ? Wq[i] : Wk[i - II * CC];
    if (i < CC * CC)
        g_wvh[i] = __float2half_rn(Wv[i]);
}

// =====================================================================
// prep: transpose x [c][n] fp32 -> xT [n][c] fp16  (64x64 smem tiles)
// =====================================================================
__global__ __launch_bounds__(256)
void prep_xt_kernel(const float* __restrict__ x)
{
    __shared__ float t[64][65];
    const long long bz = blockIdx.z;
    const int n0 = blockIdx.x * 64;
    const int c0 = blockIdx.y * 64;
    const float* src = x + bz * (long long)(CC * NN);
    __half* dst = g_xth + bz * (long long)(NN * CC);

    const int t4 = threadIdx.x & 3;
    const int r  = threadIdx.x >> 2;     // 0..63

    #pragma unroll
    for (int j = 0; j < 4; j++) {
        float4 v = *(const float4*)(src + (long long)(c0 + r) * NN + n0 + t4 * 16 + j * 4);
        t[r][t4 * 16 + j * 4 + 0] = v.x;
        t[r][t4 * 16 + j * 4 + 1] = v.y;
        t[r][t4 * 16 + j * 4 + 2] = v.z;
        t[r][t4 * 16 + j * 4 + 3] = v.w;
    }
    __syncthreads();

    const long long ob = (long long)(n0 + r) * CC + c0 + t4 * 16;
    #pragma unroll
    for (int w = 0; w < 8; w++) {
        __half2 h = __floats2half2_rn(t[t4 * 16 + 2 * w + 0][r],
                                      t[t4 * 16 + 2 * w + 1][r]);
        *(__half2*)(dst + ob + 2 * w) = h;
    }
}

// =====================================================================
// qk GEMM (fp32 SIMT) with FUSED transpose + fp16 split epilogue (r15 proven)
// =====================================================================
__global__ __launch_bounds__(256, 2)
void qk_gemm_kernel(const float* __restrict__ x)
{
    __shared__ float As[16][128];
    __shared__ float Bs[16][128];

    const int tid = threadIdx.x;
    const long long bz = blockIdx.z;
    const float* Bm = x + bz * (long long)(CC * NN);
    const int n0 = blockIdx.x * 128;
    const int tx = tid & 15;
    const int ty = tid >> 4;

    float acc[8][8];
    #pragma unroll
    for (int i = 0; i < 8; i++)
        #pragma unroll
        for (int j = 0; j < 8; j++) acc[i][j] = 0.f;

    for (int k0 = 0; k0 < CC; k0 += 16) {
        {
            const int row = tid >> 1;
            const int kc  = (tid & 1) * 8;
            const float* p = g_wqk + (long long)row * CC + k0 + kc;
            float4 v0 = *(const float4*)p;
            float4 v1 = *(const float4*)(p + 4);
            As[kc + 0][row] = v0.x; As[kc + 1][row] = v0.y;
            As[kc + 2][row] = v0.z; As[kc + 3][row] = v0.w;
            As[kc + 4][row] = v1.x; As[kc + 5][row] = v1.y;
            As[kc + 6][row] = v1.z; As[kc + 7][row] = v1.w;
        }
        {
            const int kr = tid >> 4;
            const int nc = (tid & 15) * 8;
            const float* p = Bm + (long long)(k0 + kr) * NN + n0 + nc;
            *(float4*)&Bs[kr][nc]     = *(const float4*)p;
            *(float4*)&Bs[kr][nc + 4] = *(const float4*)(p + 4);
        }
        __syncthreads();

        #pragma unroll
        for (int kk = 0; kk < 16; kk++) {
            float a[8], b[8];
            *(float4*)(a)     = *(const float4*)&As[kk][ty * 8];
            *(float4*)(a + 4) = *(const float4*)&As[kk][ty * 8 + 4];
            *(float4*)(b)     = *(const float4*)&Bs[kk][tx * 8];
            *(float4*)(b + 4) = *(const float4*)&Bs[kk][tx * 8 + 4];
            #pragma unroll
            for (int i = 0; i < 8; i++)
                #pragma unroll
                for (int j = 0; j < 8; j++)
                    acc[i][j] = fmaf(a[i], b[j], acc[i][j]);
        }
        __syncthreads();
    }

    const bool isq = (ty < 8);
    const int ib = (ty * 8) & 63;
    __half* dh = (isq ? g_qth : g_kth) + bz * (long long)(NN * II);
    __half* dl = (isq ? g_qtl : g_ktl) + bz * (long long)(NN * II);

    #pragma unroll
    for (int j = 0; j < 8; j++) {
        const int n = n0 + tx * 8 + j;
        alignas(16) __half2 H[4];
        alignas(16) __half2 L[4];
        #pragma unroll
        for (int p = 0; p < 4; p++) {
            float v0 = acc[2 * p + 0][j];
            float v1 = acc[2 * p + 1][j];
            __half h0 = __float2half_rn(v0);
            __half h1 = __float2half_rn(v1);
            __half l0 = __float2half_rn(v0 - __half2float(h0));
            __half l1 = __float2half_rn(v1 - __half2float(h1));
            H[p] = __halves2half2(h0, h1);
            L[p] = __halves2half2(l0, l1);
        }
        *(float4*)(dh + (long long)n * II + ib) = *(const float4*)H;
        *(float4*)(dl + (long long)n * II + ib) = *(const float4*)L;
    }
}

// =====================================================================
// S tile + FUSED per-tile softmax epilogue.
// S[n,m] = sum_i q[i,n]*k[i,m] via split-fp16 mma (r10-proven body).
// Epilogue: per row (n) within this 128-wide m-tile: mt = rowmax,
// st = sum exp(S - mt); store exp(S - mt) fp16 to g_ph, (mt, st) to aux.
// grid (NTM m-tiles, NTM n-tiles, BB)
// =====================================================================
#define SSTR 36
#define STILE (128 * SSTR)
#define S_SMEM (4 * STILE * 4)

__global__ __launch_bounds__(256, 2)
void s_mma_kernel(const __half* __restrict__ qth, const __half* __restrict__ qtl,
                  const __half* __restrict__ kth, const __half* __restrict__ ktl,
                  __half* __restrict__ Ph)
{
    extern __shared__ uint32_t sw[];
    __shared__ float red4[128][4];

    const int tid = threadIdx.x;
    const long long bz = blockIdx.z;
    const int tm = blockIdx.x;           // m-tile index
    qth += bz * (long long)(NN * II);
    qtl += bz * (long long)(NN * II);
    kth += bz * (long long)(NN * II);
    ktl += bz * (long long)(NN * II);
    Ph  += bz * (long long)NN * NN;

    const int n0 = blockIdx.y * 128;
    const int m0 = tm * 128;

    {
        const int lr = tid >> 1;
        const int lsg = tid & 1;
        const uint32_t base = smem_u32(sw);
        const uint32_t sd = base + (uint32_t)(lr * SSTR + lsg * 16) * 4u;
        const long long go = (long long)lr * II + lsg * 32;
        const __half* s0 = qth + (long long)n0 * II + go;
        const __half* s1 = qtl + (long long)n0 * II + go;
        const __half* s2 = kth + (long long)m0 * II + go;
        const __half* s3 = ktl + (long long)m0 * II + go;
        #pragma unroll
        for (int c = 0; c < 4; c++) {
            cp_async16(sd + 0 * STILE * 4 + c * 16, s0 + c * 8);
            cp_async16(sd + 1 * STILE * 4 + c * 16, s1 + c * 8);
            cp_async16(sd + 2 * STILE * 4 + c * 16, s2 + c * 8);
            cp_async16(sd + 3 * STILE * 4 + c * 16, s3 + c * 8);
        }
        cp_commit();
    }
    cp_wait<0>();
    __syncthreads();

    const int wid  = tid >> 5, lane = tid & 31;
    const int wm   = (wid >> 2) * 64;
    const int wn   = (wid & 3) * 32;
    const int wq   = wid & 3;            // warp position within wm group
    const int g4   = lane >> 2;
    const int tg   = lane & 3;

    float acc[4][4][4];
    #pragma unroll
    for (int i = 0; i < 4; i++)
        #pragma unroll
        for (int j = 0; j < 4; j++)
            #pragma unroll
            for (int r = 0; r < 4; r++) acc[i][j][r] = 0.f;

    const uint32_t* QH = sw;
    const uint32_t* QL = sw + STILE;
    const uint32_t* KH = sw + 2 * STILE;
    const uint32_t* KL = sw + 3 * STILE;

    #pragma unroll
    for (int p = 0; p < 3; p++) {
        const uint32_t* A_ = (p == 2) ? QL : QH;
        const uint32_t* B_ = (p == 1) ? KL : KH;
        #pragma unroll
        for (int s = 0; s < 4; s++) {
            const int kw = s * 8 + tg;
            uint32_t a[4][4], b[4][2];
            #pragma unroll
            for (int mt = 0; mt < 4; mt++) {
                const int r0 = wm + mt * 16 + g4;
                a[mt][0] = A_[r0 * SSTR + kw];
                a[mt][1] = A_[(r0 + 8) * SSTR + kw];
                a[mt][2] = A_[r0 * SSTR + kw + 4];
                a[mt][3] = A_[(r0 + 8) * SSTR + kw + 4];
            }
            #pragma unroll
            for (int nt = 0; nt < 4; nt++) {
                const int nr = wn + nt * 8 + g4;
                b[nt][0] = B_[nr * SSTR + kw];
                b[nt][1] = B_[nr * SSTR + kw + 4];
            }
            #pragma unroll
            for (int mt = 0; mt < 4; mt++)
                #pragma unroll
                for (int nt = 0; nt < 4; nt++)
                    mma168816(acc[mt][nt], a[mt], b[nt]);
        }
    }

    // ---- fused per-tile softmax epilogue ----
    // 1) per-row tile max: thread-local over (nt, pair), shfl over tg, smem over 4 warps
    #pragma unroll
    for (int mt = 0; mt < 4; mt++) {
        #pragma unroll
        for (int hf = 0; hf < 2; hf++) {
            float mx = -1e30f;
            #pragma unroll
            for (int nt = 0; nt < 4; nt++) {
                mx = fmaxf(mx, acc[mt][nt][hf * 2 + 0]);
                mx = fmaxf(mx, acc[mt][nt][hf * 2 + 1]);
            }
            mx = fmaxf(mx, __shfl_xor_sync(0xffffffffu, mx, 1));
            mx = fmaxf(mx, __shfl_xor_sync(0xffffffffu, mx, 2));
            if (tg == 0) red4[wm + mt * 16 + g4 + hf * 8][wq] = mx;
        }
    }
    __syncthreads();
    float rmax[4][2];
    #pragma unroll
    for (int mt = 0; mt < 4; mt++)
        #pragma unroll
        for (int hf = 0; hf < 2; hf++) {
            const int row = wm + mt * 16 + g4 + hf * 8;
            rmax[mt][hf] = fmaxf(fmaxf(red4[row][0], red4[row][1]),
                                 fmaxf(red4[row][2], red4[row][3]));
        }
    __syncthreads();

    // 2) exp in place + per-row tile sum
    #pragma unroll
    for (int mt = 0; mt < 4; mt++) {
        #pragma unroll
        for (int hf = 0; hf < 2; hf++) {
            float s = 0.f;
            #pragma unroll
            for (int nt = 0; nt < 4; nt++) {
                float e0 = __expf(acc[mt][nt][hf * 2 + 0] - rmax[mt][hf]);
                float e1 = __expf(acc[mt][nt][hf * 2 + 1] - rmax[mt][hf]);
                acc[mt][nt][hf * 2 + 0] = e0;
                acc[mt][nt][hf * 2 + 1] = e1;
                s += e0 + e1;
            }
            s += __shfl_xor_sync(0xffffffffu, s, 1);
            s += __shfl_xor_sync(0xffffffffu, s, 2);
            if (tg == 0) red4[wm + mt * 16 + g4 + hf * 8][wq] = s;
        }
    }
    __syncthreads();

    // 3) store exp tile fp16 + aux (m, s) per row
    float* mrow = g_mrow + (bz * NTM + tm) * (long long)NN;
    float* srow = g_srow + (bz * NTM + tm) * (long long)NN;
    #pragma unroll
    for (int mt = 0; mt < 4; mt++) {
        #pragma unroll
        for (int hf = 0; hf < 2; hf++) {
            const int row = wm + mt * 16 + g4 + hf * 8;
            const long long rb = (long long)(n0 + row) * NN;
            #pragma unroll
            for (int nt = 0; nt < 4; nt++) {
                const int col = m0 + wn + nt * 8 + 2 * tg;
                __half2 h = __floats2half2_rn(acc[mt][nt][hf * 2 + 0],
                                              acc[mt][nt][hf * 2 + 1]);
                *(__half2*)(Ph + rb + col) = h;
            }
            if (wq == 0 && tg == 0) {
                const float rs = red4[row][0] + red4[row][1] +
                                 red4[row][2] + red4[row][3];
                mrow[n0 + row] = rmax[mt][hf];
                srow[n0 + row] = rs;
            }
        }
    }
}

// =====================================================================
// normalize: per row, combine 18 per-tile (m, s) -> scale factors, apply.
// grid (BB*NN/6), block 256
// =====================================================================
#define NRM 6

__global__ __launch_bounds__(256)
void norm_kernel(__half* __restrict__ Ph)
{
    __shared__ float sm_m[NTM], sm_s[NTM], fac[NTM], red1[2];
    const int tid = threadIdx.x;

    for (int r = 0; r < NRM; r++) {
        const size_t rowg = (size_t)blockIdx.x * NRM + r;
        const size_t b = rowg / NN;
        const size_t n = rowg % NN;

        if (tid < NTM) {
            sm_m[tid] = g_mrow[(b * NTM + tid) * NN + n];
            sm_s[tid] = g_srow[(b * NTM + tid) * NN + n];
        }
        __syncthreads();
        if (tid == 0) {
            float mf = -1e30f;
            #pragma unroll
            for (int t = 0; t < NTM; t++) mf = fmaxf(mf, sm_m[t]);
            float sum = 0.f;
            #pragma unroll
            for (int t = 0; t < NTM; t++) sum += sm_s[t] * __expf(sm_m[t] - mf);
            red1[0] = mf;
            red1[1] = 1.f / sum;
        }
        __syncthreads();
        if (tid < NTM) fac[tid] = __expf(sm_m[tid] - red1[0]) * red1[1];
        __syncthreads();

        __half2* p2 = (__half2*)(Ph + rowg * NN);
        #pragma unroll
        for (int j = 0; j < 5; j++) {
            const int e2 = tid + 256 * j;
            if (e2 < NN / 2) {
                const float f = fac[e2 >> 6];        // 64 half2 per tile
                float2 v = __half22float2(p2[e2]);
                p2[e2] = __floats2half2_rn(v.x * f, v.y * f);
            }
        }
        __syncthreads();
    }
}

// =====================================================================
// Generic fp16 NT mma kernel (round-13 proven EXACTLY)
// =====================================================================
#define HSTR 20
#define HTILE (128 * HSTR)
#define HSTAGE (2 * HTILE)
#define H_SMEM (4 * HSTAGE * 4)

template<int LD, int NCH, bool EPI>
__global__ __launch_bounds__(256, 2)
void h_nt_mma_kernel(const __half* __restrict__ A, const __half* __restrict__ Bm,
                     const float* __restrict__ X, void* __restrict__ Out,
                     const float* __restrict__ gamma_p,
                     long long sA, long long sB, long long sO)
{
    extern __shared__ uint32_t smw[];

    const int tid = threadIdx.x;
    const long long bz = blockIdx.z;
    A  += bz * sA;
    Bm += bz * sB;
    const float* Xb = X + bz * sO;
    float*  Of = (float*)Out + bz * sO;
    __half* Oh = (__half*)Out + bz * sO;

    const int m0 = blockIdx.y * 128;
    const int n0 = blockIdx.x * 128;

    const int lrow = tid >> 1;
    const int lh   = tid & 1;
    const __half* gA = A  + (long long)(m0 + lrow) * LD + lh * 16;
    const __half* gB = Bm + (long long)(n0 + lrow) * LD + lh * 16;
    const uint32_t sbase = smem_u32(smw);
    const uint32_t sA_st = sbase + (uint32_t)(lrow * HSTR + lh * 8) * 4u;
    const uint32_t sB_st = sA_st + HTILE * 4u;

#define H_ISSUE(c)                                                         \
    do {                                                                   \
        const uint32_t off_ = (uint32_t)((c) & 3) * (HSTAGE * 4u);         \
        const __half* pa_ = gA + (c) * 32;                                 \
        const __half* pb_ = gB + (c) * 32;                                 \
        cp_async16(sA_st + off_,      pa_);                                \
        cp_async16(sA_st + off_ + 16, pa_ + 8);                            \
        cp_async16(sB_st + off_,      pb_);                                \
        cp_async16(sB_st + off_ + 16, pb_ + 8);                            \
        cp_commit();                                                       \
    } while (0)

    H_ISSUE(0); H_ISSUE(1); H_ISSUE(2);

    const int wid  = tid >> 5, lane = tid & 31;
    const int wm   = (wid >> 2) * 64;
    const int wn   = (wid & 3) * 32;
    const int g4   = lane >> 2;
    const int tg   = lane & 3;

    uint32_t aAddr[4], bAddr[4];
    #pragma unroll
    for (int mt = 0; mt < 4; mt++)
        aAddr[mt] = sbase +
            (uint32_t)((wm + mt * 16 + (lane & 15)) * HSTR + (lane >> 4) * 4) * 4u;
    #pragma unroll
    for (int nt = 0; nt < 4; nt++)
        bAddr[nt] = sbase +
            (uint32_t)(HTILE + (wn + nt * 8 + (lane & 7)) * HSTR + ((lane >> 3) & 1) * 4) * 4u;

    float acc[4][4][4];
    #pragma unroll
    for (int i = 0; i < 4; i++)
        #pragma unroll
        for (int j = 0; j < 4; j++)
            #pragma unroll
            for (int r = 0; r < 4; r++) acc[i][j][r] = 0.f;

    for (int c = 0; c < NCH; c++) {
        if (c + 2 < NCH)       cp_wait<2>();
        else if (c + 1 < NCH)  cp_wait<1>();
        else                   cp_wait<0>();
        __syncthreads();

        if (c + 3 < NCH) H_ISSUE(c + 3);

        const uint32_t so = (uint32_t)(c & 3) * (HSTAGE * 4u);

        #pragma unroll
        for (int s = 0; s < 2; s++) {
            const uint32_t ko = so + (uint32_t)s * 32u;
            uint32_t a[4][4], b[4][2];
            #pragma unroll
            for (int mt = 0; mt < 4; mt++)
                ldsm_x4(a[mt], aAddr[mt] + ko);
            #pragma unroll
            for (int nt = 0; nt < 4; nt++)
                ldsm_x2(b[nt], bAddr[nt] + ko);
            #pragma unroll
            for (int mt = 0; mt < 4; mt++)
                #pragma unroll
                for (int nt = 0; nt < 4; nt++)
                    mma168816(acc[mt][nt], a[mt], b[nt]);
        }
    }

    if (EPI) {
        const float g = *gamma_p;
        #pragma unroll
        for (int mt = 0; mt < 4; mt++) {
            #pragma unroll
            for (int hf = 0; hf < 2; hf++) {
                const int m = m0 + wm + mt * 16 + g4 + hf * 8;
                const long long rb = (long long)m * NN;
                #pragma unroll
                for (int nt = 0; nt < 4; nt++) {
                    const int n = n0 + wn + nt * 8 + 2 * tg;
                    float2 xr = *(const float2*)(Xb + rb + n);
                    float2 o;
                    o.x = fmaf(g, acc[mt][nt][hf * 2 + 0], xr.x);
                    o.y = fmaf(g, acc[mt][nt][hf * 2 + 1], xr.y);
                    *(float2*)(Of + rb + n) = o;
                }
            }
        }
    } else {
        #pragma unroll
        for (int mt = 0; mt < 4; mt++) {
            #pragma unroll
            for (int hf = 0; hf < 2; hf++) {
                const int m = m0 + wm + mt * 16 + g4 + hf * 8;
                const long long rb = (long long)m * NN;
                #pragma unroll
                for (int nt = 0; nt < 4; nt++) {
                    const int n = n0 + wn + nt * 8 + 2 * tg;
                    __half2 h = __floats2half2_rn(acc[mt][nt][hf * 2 + 0],
                                                  acc[mt][nt][hf * 2 + 1]);
                    *(__half2*)(Oh + rb + n) = h;
                }
            }
        }
    }
#undef H_ISSUE
}

// ---------------- launch ----------------
extern "C" void kernel_launch(void* const* d_in, const int* in_sizes, int n_in,
                              void* d_out, int out_size)
{
    const float* x     = (const float*)d_in[0];   // (16,512,48,48)
    const float* Wq    = (const float*)d_in[1];   // (64,512)
    const float* Wk    = (const float*)d_in[2];   // (64,512)
    const float* Wv    = (const float*)d_in[3];   // (512,512)
    const float* gamma = (const float*)d_in[4];   // (1,)
    float* out = (float*)d_out;

    __half *ph, *vh, *qth, *qtl, *kth, *ktl, *xth, *wvh;
    cudaGetSymbolAddress((void**)&ph,  g_ph);
    cudaGetSymbolAddress((void**)&vh,  g_vh);
    cudaGetSymbolAddress((void**)&qth, g_qth);
    cudaGetSymbolAddress((void**)&qtl, g_qtl);
    cudaGetSymbolAddress((void**)&kth, g_kth);
    cudaGetSymbolAddress((void**)&ktl, g_ktl);
    cudaGetSymbolAddress((void**)&xth, g_xth);
    cudaGetSymbolAddress((void**)&wvh, g_wvh);

    const long long sX = (long long)CC * NN;

    dim3 blk(256);

    // prep: [Wq;Wk] concat, Wv->fp16; x -> xT fp16
    prep_w_kernel<<<(CC * CC + 255) / 256, 256>>>(Wq, Wk, Wv);
    prep_xt_kernel<<<dim3(NN / 64, CC / 64, BB), blk>>>(x);

    // [q;k] GEMM with fused transpose + hi/lo split epilogue
    qk_gemm_kernel<<<dim3(NN / 128, 1, BB), blk>>>(x);

    // v = Wv @ xT : fp16 mma (round-13 proven config)
    cudaFuncSetAttribute(h_nt_mma_kernel<CC, CC / 32, false>,
                         cudaFuncAttributeMaxDynamicSharedMemorySize, H_SMEM);
    h_nt_mma_kernel<CC, CC / 32, false><<<dim3(NN / 128, CC / 128, BB), blk, H_SMEM>>>(
        wvh, xth, nullptr, vh, nullptr, 0, (long long)NN * CC, sX);

    // S tiles + fused per-tile softmax -> unnormalized exp fp16 + aux
    cudaFuncSetAttribute(s_mma_kernel,
                         cudaFuncAttributeMaxDynamicSharedMemorySize, S_SMEM);
    s_mma_kernel<<<dim3(NTM, NTM, BB), blk, S_SMEM>>>(
        qth, qtl, kth, ktl, ph);

    // normalize P rows from per-tile (m, s)
    norm_kernel<<<BB * NN / NRM, 256>>>(ph);

    // out = gamma * (V @ P^T) + x  (fp16 mma, round-13 proven config)
    cudaFuncSetAttribute(h_nt_mma_kernel<NN, NN / 32, true>,
                         cudaFuncAttributeMaxDynamicSharedMemorySize, H_SMEM);
    h_nt_mma_kernel<NN, NN / 32, true><<<dim3(NN / 128, CC / 128, BB), blk, H_SMEM>>>(
        vh, ph, x, out, gamma, sX, (long long)NN * NN, sX);
}